// round 5
// baseline (speedup 1.0000x reference)
#include <cuda_runtime.h>
#include <math.h>
#include <stdint.h>

#define DIM 128
#define MAXN 50000
#define BM 128
#define BN 64
#define BK 32
#define NT 256
#define SA 132                       // As row stride (floats)
#define AS_BYTES (2 * BK * SA * 4)   // 33792
#define WS_BYTES (2 * BK * BN * 8)   // 32768
#define SMEM_GEMM (AS_BYTES + WS_BYTES)

// scratch (device globals; allocation-free rule)
__device__ float g_H  [(size_t)MAXN * DIM];
__device__ float g_X  [(size_t)MAXN * DIM];
__device__ float g_AGG[(size_t)MAXN * DIM];
__device__ float g_OUT[(size_t)MAXN * DIM];
__device__ float g_Z  [(size_t)MAXN * DIM];
__device__ float g_RX [(size_t)MAXN * DIM];

// ---------------- packed f32x2 helpers --------------------------------------
__device__ __forceinline__ void ffma2(uint64_t& acc, uint64_t a, uint64_t b) {
    asm("fma.rn.f32x2 %0, %1, %2, %0;" : "+l"(acc) : "l"(a), "l"(b));
}
__device__ __forceinline__ uint64_t dup2(float a) {
    uint64_t d;
    asm("mov.b64 %0, {%1, %1};" : "=l"(d) : "f"(a));
    return d;
}
__device__ __forceinline__ float2 unpk(uint64_t v) {
    float2 f;
    asm("mov.b64 {%0, %1}, %2;" : "=f"(f.x), "=f"(f.y) : "l"(v));
    return f;
}
__device__ __forceinline__ float sigf(float x) { return 1.f / (1.f + __expf(-x)); }

// ---------------- GEMM template ---------------------------------------------
// C[M x 128] = A[M x K] @ W[K x 128] with epilogue; K = NCH*32 (128 or 256).
// For K=256, A = [A0 | A1] (chunks 0-3 from A0, 4-7 from A1), W = [W0 ; W1].
// EPI: 0=relu(+b) 1=+b 2=sigmoid(+b[+b2])[*aux1] 3=final gate
template<int EPI, int NCH>
__global__ void __launch_bounds__(NT, 2)
gemm_kernel(const float* __restrict__ A0, const float* __restrict__ A1,
            const float* __restrict__ W0, const float* __restrict__ W1,
            const float* __restrict__ b1, const float* __restrict__ b2,
            const float* __restrict__ aux1, const float* __restrict__ aux2,
            float* __restrict__ out, int nrows)
{
    extern __shared__ char smc[];
    float* As = (float*)smc;                      // [2][BK][SA] transposed: As[k][m]
    uint64_t* Ws = (uint64_t*)(smc + AS_BYTES);   // [2][BK][BN] dup'd pairs
    const int t = threadIdx.x;
    const int tx = t & 15;        // col group: cols 4*tx .. 4*tx+3
    const int ty = t >> 4;        // row group: rows 8*ty .. 8*ty+7
    const int row0 = blockIdx.x * BM;
    const int n0 = blockIdx.y * BN;

    // loader roles
    const int ar = t >> 1;        // A row 0..127
    const int ah = t & 1;
    const int wk = t >> 3;        // W k-row 0..31
    const int wc = t & 7;         // col octet

    float4 av[4];
    float4 wv0, wv1;

    auto ldA = [&](int cc) {
        const float* src = (NCH == 8 && cc >= 4) ? A1 : A0;
        int kb = (NCH == 8 && cc >= 4) ? (cc - 4) * BK : cc * BK;
        int r = row0 + ar;
        if (r < nrows) {
            const float* p = src + (size_t)r * DIM + kb + ah * 4;
            av[0] = *(const float4*)(p);
            av[1] = *(const float4*)(p + 8);
            av[2] = *(const float4*)(p + 16);
            av[3] = *(const float4*)(p + 24);
        } else {
            av[0] = av[1] = av[2] = av[3] = make_float4(0.f, 0.f, 0.f, 0.f);
        }
    };
    auto stsA = [&](int buf) {
        float* d = As + buf * (BK * SA);
        #pragma unroll
        for (int q = 0; q < 4; q++) {
            int k = ah * 4 + q * 8;
            d[(k + 0) * SA + ar] = av[q].x;
            d[(k + 1) * SA + ar] = av[q].y;
            d[(k + 2) * SA + ar] = av[q].z;
            d[(k + 3) * SA + ar] = av[q].w;
        }
    };
    auto ldW = [&](int cc) {
        const float* src = (NCH == 8 && cc >= 4) ? W1 : W0;
        int kb = (NCH == 8 && cc >= 4) ? (cc - 4) * BK : cc * BK;
        const float* p = src + (size_t)(kb + wk) * DIM + n0 + wc * 8;
        wv0 = *(const float4*)(p);
        wv1 = *(const float4*)(p + 4);
    };
    auto stsW = [&](int buf) {
        ulonglong2* d = (ulonglong2*)(Ws + buf * (BK * BN) + wk * BN + wc * 8);
        d[0] = make_ulonglong2(dup2(wv0.x), dup2(wv0.y));
        d[1] = make_ulonglong2(dup2(wv0.z), dup2(wv0.w));
        d[2] = make_ulonglong2(dup2(wv1.x), dup2(wv1.y));
        d[3] = make_ulonglong2(dup2(wv1.z), dup2(wv1.w));
    };

    uint64_t acc[4][4];
    #pragma unroll
    for (int i = 0; i < 4; i++)
        #pragma unroll
        for (int j = 0; j < 4; j++) acc[i][j] = 0ull;

    ldA(0); ldW(0);
    stsA(0); stsW(0);

    for (int cc = 0; cc < NCH; cc++) {
        __syncthreads();
        if (cc + 1 < NCH) { ldA(cc + 1); ldW(cc + 1); }
        const float* as = As + (cc & 1) * (BK * SA) + 8 * ty;
        const uint64_t* ws = Ws + (cc & 1) * (BK * BN) + 4 * tx;
        #pragma unroll
        for (int k = 0; k < BK; k++) {
            ulonglong2 aA = *(const ulonglong2*)(as + k * SA);
            ulonglong2 aB = *(const ulonglong2*)(as + k * SA + 4);
            ulonglong2 w01 = *(const ulonglong2*)(ws + k * BN);
            ulonglong2 w23 = *(const ulonglong2*)(ws + k * BN + 2);
            ffma2(acc[0][0], aA.x, w01.x); ffma2(acc[0][1], aA.x, w01.y);
            ffma2(acc[0][2], aA.x, w23.x); ffma2(acc[0][3], aA.x, w23.y);
            ffma2(acc[1][0], aA.y, w01.x); ffma2(acc[1][1], aA.y, w01.y);
            ffma2(acc[1][2], aA.y, w23.x); ffma2(acc[1][3], aA.y, w23.y);
            ffma2(acc[2][0], aB.x, w01.x); ffma2(acc[2][1], aB.x, w01.y);
            ffma2(acc[2][2], aB.x, w23.x); ffma2(acc[2][3], aB.x, w23.y);
            ffma2(acc[3][0], aB.y, w01.x); ffma2(acc[3][1], aB.y, w01.y);
            ffma2(acc[3][2], aB.y, w23.x); ffma2(acc[3][3], aB.y, w23.y);
        }
        if (cc + 1 < NCH) { stsA((cc + 1) & 1); stsW((cc + 1) & 1); }
    }

    // ---------------- epilogue ----------------
    const int col = n0 + 4 * tx;
    float4 bb = *(const float4*)(b1 + col);
    if (b2 != nullptr) {
        float4 b2v = *(const float4*)(b2 + col);
        bb.x += b2v.x; bb.y += b2v.y; bb.z += b2v.z; bb.w += b2v.w;
    }

    #pragma unroll
    for (int rp = 0; rp < 4; rp++) {
        float2 p0 = unpk(acc[rp][0]), p1 = unpk(acc[rp][1]);
        float2 p2 = unpk(acc[rp][2]), p3 = unpk(acc[rp][3]);
        float vr[2][4] = {{p0.x, p1.x, p2.x, p3.x}, {p0.y, p1.y, p2.y, p3.y}};
        #pragma unroll
        for (int h = 0; h < 2; h++) {
            int m = row0 + 8 * ty + 2 * rp + h;
            if (m >= nrows) continue;
            float v[4] = {vr[h][0] + bb.x, vr[h][1] + bb.y,
                          vr[h][2] + bb.z, vr[h][3] + bb.w};
            float4 o;
            if (EPI == 0) {
                o = make_float4(fmaxf(v[0], 0.f), fmaxf(v[1], 0.f),
                                fmaxf(v[2], 0.f), fmaxf(v[3], 0.f));
            } else if (EPI == 1) {
                o = make_float4(v[0], v[1], v[2], v[3]);
            } else if (EPI == 2) {
                o = make_float4(sigf(v[0]), sigf(v[1]), sigf(v[2]), sigf(v[3]));
                if (aux1 != nullptr) {
                    float4 xv = *(const float4*)(aux1 + (size_t)m * DIM + col);
                    o.x *= xv.x; o.y *= xv.y; o.z *= xv.z; o.w *= xv.w;
                }
            } else {  // EPI == 3: y = (1-z)*x + z*tanh(v)
                float4 zv = *(const float4*)(aux1 + (size_t)m * DIM + col);
                float4 xv = *(const float4*)(aux2 + (size_t)m * DIM + col);
                o.x = (1.f - zv.x) * xv.x + zv.x * tanhf(v[0]);
                o.y = (1.f - zv.y) * xv.y + zv.y * tanhf(v[1]);
                o.z = (1.f - zv.z) * xv.z + zv.z * tanhf(v[2]);
                o.w = (1.f - zv.w) * xv.w + zv.w * tanhf(v[3]);
            }
            *(float4*)(out + (size_t)m * DIM + col) = o;
        }
    }
}

// ---------------- scatter ----------------------------------------------------
__global__ void __launch_bounds__(NT)
scatter_kernel(const int* __restrict__ rows, const int* __restrict__ cols,
               const float* __restrict__ vals,
               const float* __restrict__ X, float* __restrict__ AGG, int E)
{
    int w = blockIdx.x * (NT / 32) + (threadIdx.x >> 5);
    int lane = threadIdx.x & 31;
    if (w >= E) return;
    int r = __ldg(rows + w);
    int c = __ldg(cols + w);
    float v = __ldg(vals + w);
    float4 xv = reinterpret_cast<const float4*>(X + (size_t)c * DIM)[lane];
    float* dst = AGG + (size_t)r * DIM + 4 * lane;
    asm volatile("red.global.add.v4.f32 [%0], {%1, %2, %3, %4};"
                 :: "l"(dst), "f"(v * xv.x), "f"(v * xv.y), "f"(v * xv.z), "f"(v * xv.w)
                 : "memory");
}

// ---------------- launch -----------------------------------------------------
extern "C" void kernel_launch(void* const* d_in, const int* in_sizes, int n_in,
                              void* d_out, int out_size)
{
    const float* x_in = (const float*)d_in[0];
    const int*   rows = (const int*)d_in[1];
    const int*   cols = (const int*)d_in[2];
    const float* vals = (const float*)d_in[3];
    const float* m1W1 = (const float*)d_in[4];
    const float* m1b1 = (const float*)d_in[5];
    const float* m1W2 = (const float*)d_in[6];
    const float* m1b2 = (const float*)d_in[7];
    const float* m2W1 = (const float*)d_in[8];
    const float* m2b1 = (const float*)d_in[9];
    const float* m2W2 = (const float*)d_in[10];
    const float* m2b2 = (const float*)d_in[11];
    const float* Wu1 = (const float*)d_in[12];
    const float* bu1 = (const float*)d_in[13];
    const float* Wu2 = (const float*)d_in[14];
    const float* bu2 = (const float*)d_in[15];
    const float* Wr1 = (const float*)d_in[16];
    const float* br1 = (const float*)d_in[17];
    const float* Wr2 = (const float*)d_in[18];
    const float* br2 = (const float*)d_in[19];
    const float* Wo1 = (const float*)d_in[20];
    const float* bo1 = (const float*)d_in[21];
    const float* Wo2 = (const float*)d_in[22];
    const float* bo2 = (const float*)d_in[23];

    int n = in_sizes[0] / DIM;
    int E = in_sizes[1];
    float* y = (float*)d_out;

    float *H, *X, *AGG, *OUT, *Z, *RX;
    cudaGetSymbolAddress((void**)&H, g_H);
    cudaGetSymbolAddress((void**)&X, g_X);
    cudaGetSymbolAddress((void**)&AGG, g_AGG);
    cudaGetSymbolAddress((void**)&OUT, g_OUT);
    cudaGetSymbolAddress((void**)&Z, g_Z);
    cudaGetSymbolAddress((void**)&RX, g_RX);

    cudaFuncSetAttribute(gemm_kernel<0, 4>, cudaFuncAttributeMaxDynamicSharedMemorySize, SMEM_GEMM);
    cudaFuncSetAttribute(gemm_kernel<1, 4>, cudaFuncAttributeMaxDynamicSharedMemorySize, SMEM_GEMM);
    cudaFuncSetAttribute(gemm_kernel<2, 8>, cudaFuncAttributeMaxDynamicSharedMemorySize, SMEM_GEMM);
    cudaFuncSetAttribute(gemm_kernel<3, 8>, cudaFuncAttributeMaxDynamicSharedMemorySize, SMEM_GEMM);

    dim3 grid((n + BM - 1) / BM, DIM / BN);

    cudaMemsetAsync(AGG, 0, (size_t)n * DIM * sizeof(float));

    // H = relu(x_in @ m1W1 + b1); X = H @ m1W2 + b2
    gemm_kernel<0, 4><<<grid, NT, SMEM_GEMM>>>(x_in, nullptr, m1W1, nullptr,
                                               m1b1, nullptr, nullptr, nullptr, H, n);
    gemm_kernel<1, 4><<<grid, NT, SMEM_GEMM>>>(H, nullptr, m1W2, nullptr,
                                               m1b2, nullptr, nullptr, nullptr, X, n);
    // AGG[rows] += vals * X[cols]
    scatter_kernel<<<(E + 7) / 8, NT>>>(rows, cols, vals, X, AGG, E);
    // H = relu(AGG @ m2W1 + b1); OUT = H @ m2W2 + b2
    gemm_kernel<0, 4><<<grid, NT, SMEM_GEMM>>>(AGG, nullptr, m2W1, nullptr,
                                               m2b1, nullptr, nullptr, nullptr, H, n);
    gemm_kernel<1, 4><<<grid, NT, SMEM_GEMM>>>(H, nullptr, m2W2, nullptr,
                                               m2b2, nullptr, nullptr, nullptr, OUT, n);
    // Z  = sigmoid(OUT@Wu1 + X@Wu2 + bu1 + bu2)
    gemm_kernel<2, 8><<<grid, NT, SMEM_GEMM>>>(OUT, X, Wu1, Wu2,
                                               bu1, bu2, nullptr, nullptr, Z, n);
    // RX = sigmoid(OUT@Wr1 + X@Wr2 + br1 + br2) * X
    gemm_kernel<2, 8><<<grid, NT, SMEM_GEMM>>>(OUT, X, Wr1, Wr2,
                                               br1, br2, X, nullptr, RX, n);
    // y = (1-Z)*X + Z*tanh(OUT@Wo1 + RX@Wo2 + bo1 + bo2)
    gemm_kernel<3, 8><<<grid, NT, SMEM_GEMM>>>(OUT, RX, Wo1, Wo2,
                                               bo1, bo2, Z, X, y, n);
}

// round 6
// speedup vs baseline: 1.4357x; 1.4357x over previous
#include <cuda_runtime.h>
#include <math.h>
#include <stdint.h>

#define DIM 128
#define MAXN 50000
#define BM 128
#define BK 16
#define NT 256
#define AS_U64  (BK * BM)                 // per buffer, u64 elems (16KB)
#define WS_F32  (BK * DIM)                // per buffer, floats (8KB)
#define SMEM_GEMM (2 * AS_U64 * 8 + 2 * WS_F32 * 4)   // 49152

// scratch (device globals; allocation-free rule)
__device__ float g_H  [(size_t)MAXN * DIM];
__device__ float g_X  [(size_t)MAXN * DIM];
__device__ float g_AGG[(size_t)MAXN * DIM];
__device__ float g_OUT[(size_t)MAXN * DIM];
__device__ float g_Z  [(size_t)MAXN * DIM];
__device__ float g_RX [(size_t)MAXN * DIM];

// ---------------- packed f32x2 helpers --------------------------------------
__device__ __forceinline__ void ffma2(uint64_t& acc, uint64_t a, uint64_t b) {
    asm("fma.rn.f32x2 %0, %1, %2, %0;" : "+l"(acc) : "l"(a), "l"(b));
}
__device__ __forceinline__ uint64_t dup2(float a) {
    uint64_t d;
    asm("mov.b64 %0, {%1, %1};" : "=l"(d) : "f"(a));
    return d;
}
__device__ __forceinline__ float2 unpk(uint64_t v) {
    float2 f;
    asm("mov.b64 {%0, %1}, %2;" : "=f"(f.x), "=f"(f.y) : "l"(v));
    return f;
}
__device__ __forceinline__ float sigf(float x) { return 1.f / (1.f + __expf(-x)); }

// ---------------- GEMM template ---------------------------------------------
// C[M x 128] = A[M x K] @ W[K x 128] + epilogue; K = NCH*16 (NCH=8 or 16).
// For NCH=16: A = [A0 | A1], W = [W0 ; W1].
// Thread (tx,ty): rows 8*ty..8*ty+7, col pairs (2*tx+32g, 2*tx+1+32g), g=0..3.
// EPI: 0=relu(+b) 1=+b 2=sigmoid(+b[+b2])[*aux1] 3=final gate
template<int EPI, int NCH>
__global__ void __launch_bounds__(NT, 2)
gemm_kernel(const float* __restrict__ A0, const float* __restrict__ A1,
            const float* __restrict__ W0, const float* __restrict__ W1,
            const float* __restrict__ b1, const float* __restrict__ b2,
            const float* __restrict__ aux1, const float* __restrict__ aux2,
            float* __restrict__ out, int nrows)
{
    extern __shared__ char smc[];
    uint64_t* As = (uint64_t*)smc;                    // [2][BK][BM] dup'd
    float*    Ws = (float*)(smc + 2 * AS_U64 * 8);    // [2][BK][DIM] plain
    const int t  = threadIdx.x;
    const int tx = t & 15;
    const int ty = t >> 4;
    const int row0 = blockIdx.x * BM;

    // loader roles
    const int ar = t >> 1;       // A row 0..127
    const int ah = t & 1;        // k half: 8 floats
    const int wr = t >> 4;       // W k-row 0..15
    const int wc = t & 15;       // col octet

    float4 av0, av1, wv0, wv1;

    auto ldA = [&](int cc) {
        const float* src = (NCH == 16 && cc >= 8) ? A1 : A0;
        int kb = ((NCH == 16) ? (cc & 7) : cc) * BK;
        int r = row0 + ar;
        if (r < nrows) {
            const float* p = src + (size_t)r * DIM + kb + ah * 8;
            av0 = *(const float4*)(p);
            av1 = *(const float4*)(p + 4);
        } else {
            av0 = av1 = make_float4(0.f, 0.f, 0.f, 0.f);
        }
    };
    auto stsA = [&](int buf) {
        uint64_t* d = As + buf * AS_U64 + (ah * 8) * BM + ar;
        d[0 * BM] = dup2(av0.x); d[1 * BM] = dup2(av0.y);
        d[2 * BM] = dup2(av0.z); d[3 * BM] = dup2(av0.w);
        d[4 * BM] = dup2(av1.x); d[5 * BM] = dup2(av1.y);
        d[6 * BM] = dup2(av1.z); d[7 * BM] = dup2(av1.w);
    };
    auto ldW = [&](int cc) {
        const float* src = (NCH == 16 && cc >= 8) ? W1 : W0;
        int kb = ((NCH == 16) ? (cc & 7) : cc) * BK;
        const float* p = src + (size_t)(kb + wr) * DIM + wc * 8;
        wv0 = *(const float4*)(p);
        wv1 = *(const float4*)(p + 4);
    };
    auto stsW = [&](int buf) {
        float* d = Ws + buf * WS_F32 + wr * DIM + wc * 8;
        *(float4*)(d)     = wv0;
        *(float4*)(d + 4) = wv1;
    };

    uint64_t acc[8][4];
    #pragma unroll
    for (int i = 0; i < 8; i++)
        #pragma unroll
        for (int j = 0; j < 4; j++) acc[i][j] = 0ull;

    ldA(0); ldW(0);
    stsA(0); stsW(0);

    for (int cc = 0; cc < NCH; cc++) {
        __syncthreads();
        if (cc + 1 < NCH) { ldA(cc + 1); ldW(cc + 1); }
        const uint64_t* as = As + (cc & 1) * AS_U64 + 8 * ty;
        const float*    ws = Ws + (cc & 1) * WS_F32 + 2 * tx;
        #pragma unroll
        for (int k = 0; k < BK; k++) {
            ulonglong2 a01 = *(const ulonglong2*)(as + k * BM);
            ulonglong2 a23 = *(const ulonglong2*)(as + k * BM + 2);
            ulonglong2 a45 = *(const ulonglong2*)(as + k * BM + 4);
            ulonglong2 a67 = *(const ulonglong2*)(as + k * BM + 6);
            uint64_t w0 = *(const uint64_t*)(ws + k * DIM);
            uint64_t w1 = *(const uint64_t*)(ws + k * DIM + 32);
            uint64_t w2 = *(const uint64_t*)(ws + k * DIM + 64);
            uint64_t w3 = *(const uint64_t*)(ws + k * DIM + 96);
            ffma2(acc[0][0], a01.x, w0); ffma2(acc[0][1], a01.x, w1);
            ffma2(acc[0][2], a01.x, w2); ffma2(acc[0][3], a01.x, w3);
            ffma2(acc[1][0], a01.y, w0); ffma2(acc[1][1], a01.y, w1);
            ffma2(acc[1][2], a01.y, w2); ffma2(acc[1][3], a01.y, w3);
            ffma2(acc[2][0], a23.x, w0); ffma2(acc[2][1], a23.x, w1);
            ffma2(acc[2][2], a23.x, w2); ffma2(acc[2][3], a23.x, w3);
            ffma2(acc[3][0], a23.y, w0); ffma2(acc[3][1], a23.y, w1);
            ffma2(acc[3][2], a23.y, w2); ffma2(acc[3][3], a23.y, w3);
            ffma2(acc[4][0], a45.x, w0); ffma2(acc[4][1], a45.x, w1);
            ffma2(acc[4][2], a45.x, w2); ffma2(acc[4][3], a45.x, w3);
            ffma2(acc[5][0], a45.y, w0); ffma2(acc[5][1], a45.y, w1);
            ffma2(acc[5][2], a45.y, w2); ffma2(acc[5][3], a45.y, w3);
            ffma2(acc[6][0], a67.x, w0); ffma2(acc[6][1], a67.x, w1);
            ffma2(acc[6][2], a67.x, w2); ffma2(acc[6][3], a67.x, w3);
            ffma2(acc[7][0], a67.y, w0); ffma2(acc[7][1], a67.y, w1);
            ffma2(acc[7][2], a67.y, w2); ffma2(acc[7][3], a67.y, w3);
        }
        if (cc + 1 < NCH) { stsA((cc + 1) & 1); stsW((cc + 1) & 1); }
    }

    // ---------------- epilogue ----------------
    float2 bb[4];
    #pragma unroll
    for (int g = 0; g < 4; g++) {
        int col = 2 * tx + 32 * g;
        bb[g] = *(const float2*)(b1 + col);
        if (b2 != nullptr) {
            float2 b2v = *(const float2*)(b2 + col);
            bb[g].x += b2v.x; bb[g].y += b2v.y;
        }
    }

    #pragma unroll
    for (int i = 0; i < 8; i++) {
        int m = row0 + 8 * ty + i;
        if (m >= nrows) continue;
        #pragma unroll
        for (int g = 0; g < 4; g++) {
            int col = 2 * tx + 32 * g;
            float2 p = unpk(acc[i][g]);
            float vx = p.x + bb[g].x;
            float vy = p.y + bb[g].y;
            float2 o;
            if (EPI == 0) {
                o = make_float2(fmaxf(vx, 0.f), fmaxf(vy, 0.f));
            } else if (EPI == 1) {
                o = make_float2(vx, vy);
            } else if (EPI == 2) {
                o = make_float2(sigf(vx), sigf(vy));
                if (aux1 != nullptr) {
                    float2 xv = *(const float2*)(aux1 + (size_t)m * DIM + col);
                    o.x *= xv.x; o.y *= xv.y;
                }
            } else {  // EPI == 3: y = (1-z)*x + z*tanh(v)
                float2 zv = *(const float2*)(aux1 + (size_t)m * DIM + col);
                float2 xv = *(const float2*)(aux2 + (size_t)m * DIM + col);
                o.x = (1.f - zv.x) * xv.x + zv.x * tanhf(vx);
                o.y = (1.f - zv.y) * xv.y + zv.y * tanhf(vy);
            }
            *(float2*)(out + (size_t)m * DIM + col) = o;
        }
    }
}

// ---------------- scatter ----------------------------------------------------
__global__ void __launch_bounds__(NT)
scatter_kernel(const int* __restrict__ rows, const int* __restrict__ cols,
               const float* __restrict__ vals,
               const float* __restrict__ X, float* __restrict__ AGG, int E)
{
    int w = blockIdx.x * (NT / 32) + (threadIdx.x >> 5);
    int lane = threadIdx.x & 31;
    if (w >= E) return;
    int r = __ldg(rows + w);
    int c = __ldg(cols + w);
    float v = __ldg(vals + w);
    float4 xv = reinterpret_cast<const float4*>(X + (size_t)c * DIM)[lane];
    float* dst = AGG + (size_t)r * DIM + 4 * lane;
    asm volatile("red.global.add.v4.f32 [%0], {%1, %2, %3, %4};"
                 :: "l"(dst), "f"(v * xv.x), "f"(v * xv.y), "f"(v * xv.z), "f"(v * xv.w)
                 : "memory");
}

// ---------------- launch -----------------------------------------------------
extern "C" void kernel_launch(void* const* d_in, const int* in_sizes, int n_in,
                              void* d_out, int out_size)
{
    const float* x_in = (const float*)d_in[0];
    const int*   rows = (const int*)d_in[1];
    const int*   cols = (const int*)d_in[2];
    const float* vals = (const float*)d_in[3];
    const float* m1W1 = (const float*)d_in[4];
    const float* m1b1 = (const float*)d_in[5];
    const float* m1W2 = (const float*)d_in[6];
    const float* m1b2 = (const float*)d_in[7];
    const float* m2W1 = (const float*)d_in[8];
    const float* m2b1 = (const float*)d_in[9];
    const float* m2W2 = (const float*)d_in[10];
    const float* m2b2 = (const float*)d_in[11];
    const float* Wu1 = (const float*)d_in[12];
    const float* bu1 = (const float*)d_in[13];
    const float* Wu2 = (const float*)d_in[14];
    const float* bu2 = (const float*)d_in[15];
    const float* Wr1 = (const float*)d_in[16];
    const float* br1 = (const float*)d_in[17];
    const float* Wr2 = (const float*)d_in[18];
    const float* br2 = (const float*)d_in[19];
    const float* Wo1 = (const float*)d_in[20];
    const float* bo1 = (const float*)d_in[21];
    const float* Wo2 = (const float*)d_in[22];
    const float* bo2 = (const float*)d_in[23];

    int n = in_sizes[0] / DIM;
    int E = in_sizes[1];
    float* y = (float*)d_out;

    float *H, *X, *AGG, *OUT, *Z, *RX;
    cudaGetSymbolAddress((void**)&H, g_H);
    cudaGetSymbolAddress((void**)&X, g_X);
    cudaGetSymbolAddress((void**)&AGG, g_AGG);
    cudaGetSymbolAddress((void**)&OUT, g_OUT);
    cudaGetSymbolAddress((void**)&Z, g_Z);
    cudaGetSymbolAddress((void**)&RX, g_RX);

    cudaFuncSetAttribute(gemm_kernel<0, 8>,  cudaFuncAttributeMaxDynamicSharedMemorySize, SMEM_GEMM);
    cudaFuncSetAttribute(gemm_kernel<1, 8>,  cudaFuncAttributeMaxDynamicSharedMemorySize, SMEM_GEMM);
    cudaFuncSetAttribute(gemm_kernel<2, 16>, cudaFuncAttributeMaxDynamicSharedMemorySize, SMEM_GEMM);
    cudaFuncSetAttribute(gemm_kernel<3, 16>, cudaFuncAttributeMaxDynamicSharedMemorySize, SMEM_GEMM);

    int nb = (n + BM - 1) / BM;

    cudaMemsetAsync(AGG, 0, (size_t)n * DIM * sizeof(float));

    // H = relu(x_in @ m1W1 + b1); X = H @ m1W2 + b2
    gemm_kernel<0, 8><<<nb, NT, SMEM_GEMM>>>(x_in, nullptr, m1W1, nullptr,
                                             m1b1, nullptr, nullptr, nullptr, H, n);
    gemm_kernel<1, 8><<<nb, NT, SMEM_GEMM>>>(H, nullptr, m1W2, nullptr,
                                             m1b2, nullptr, nullptr, nullptr, X, n);
    // AGG[rows] += vals * X[cols]
    scatter_kernel<<<(E + 7) / 8, NT>>>(rows, cols, vals, X, AGG, E);
    // H = relu(AGG @ m2W1 + b1); OUT = H @ m2W2 + b2
    gemm_kernel<0, 8><<<nb, NT, SMEM_GEMM>>>(AGG, nullptr, m2W1, nullptr,
                                             m2b1, nullptr, nullptr, nullptr, H, n);
    gemm_kernel<1, 8><<<nb, NT, SMEM_GEMM>>>(H, nullptr, m2W2, nullptr,
                                             m2b2, nullptr, nullptr, nullptr, OUT, n);
    // Z  = sigmoid(OUT@Wu1 + X@Wu2 + bu)
    gemm_kernel<2, 16><<<nb, NT, SMEM_GEMM>>>(OUT, X, Wu1, Wu2,
                                              bu1, bu2, nullptr, nullptr, Z, n);
    // RX = sigmoid(OUT@Wr1 + X@Wr2 + br) * X
    gemm_kernel<2, 16><<<nb, NT, SMEM_GEMM>>>(OUT, X, Wr1, Wr2,
                                              br1, br2, X, nullptr, RX, n);
    // y = (1-Z)*X + Z*tanh(OUT@Wo1 + RX@Wo2 + bo)
    gemm_kernel<3, 16><<<nb, NT, SMEM_GEMM>>>(OUT, RX, Wo1, Wo2,
                                              bo1, bo2, Z, X, y, n);
}

// round 8
// speedup vs baseline: 1.5518x; 1.0809x over previous
#include <cuda_runtime.h>
#include <math.h>
#include <stdint.h>

#define DIM 128
#define MAXN 50000
#define MAXE 1600000
#define BM 128
#define BK 16
#define NT 256
#define AS_U64  (BK * BM)                 // per buffer, u64 elems (16KB)
#define WS_F32  (BK * DIM)                // per buffer, floats (8KB)
#define SMEM_GEMM (2 * AS_U64 * 8 + 2 * WS_F32 * 4)   // 49152

// scratch (device globals; allocation-free rule)
__device__ float g_H  [(size_t)MAXN * DIM];
__device__ float g_X  [(size_t)MAXN * DIM];
__device__ float g_AGG[(size_t)MAXN * DIM];
__device__ float g_OUT[(size_t)MAXN * DIM];
__device__ float g_Z  [(size_t)MAXN * DIM];
__device__ float g_RX [(size_t)MAXN * DIM];
__device__ int   g_off [MAXN + 1];     // CSR offsets (counts -> exclusive scan)
__device__ int   g_head[MAXN];         // running insert heads
__device__ int   g_ecol[MAXE];         // bucketed cols
__device__ float g_eval[MAXE];         // bucketed vals

// ---------------- packed f32x2 helpers --------------------------------------
__device__ __forceinline__ void ffma2(uint64_t& acc, uint64_t a, uint64_t b) {
    asm("fma.rn.f32x2 %0, %1, %2, %0;" : "+l"(acc) : "l"(a), "l"(b));
}
__device__ __forceinline__ uint64_t dup2(float a) {
    uint64_t d;
    asm("mov.b64 %0, {%1, %1};" : "=l"(d) : "f"(a));
    return d;
}
__device__ __forceinline__ float2 unpk(uint64_t v) {
    float2 f;
    asm("mov.b64 {%0, %1}, %2;" : "=f"(f.x), "=f"(f.y) : "l"(v));
    return f;
}
__device__ __forceinline__ float sigf(float x) { return 1.f / (1.f + __expf(-x)); }

// ---------------- GEMM template (unchanged from R6) --------------------------
template<int EPI, int NCH>
__global__ void __launch_bounds__(NT, 2)
gemm_kernel(const float* __restrict__ A0, const float* __restrict__ A1,
            const float* __restrict__ W0, const float* __restrict__ W1,
            const float* __restrict__ b1, const float* __restrict__ b2,
            const float* __restrict__ aux1, const float* __restrict__ aux2,
            float* __restrict__ out, int nrows)
{
    extern __shared__ char smc[];
    uint64_t* As = (uint64_t*)smc;                    // [2][BK][BM] dup'd
    float*    Ws = (float*)(smc + 2 * AS_U64 * 8);    // [2][BK][DIM] plain
    const int t  = threadIdx.x;
    const int tx = t & 15;
    const int ty = t >> 4;
    const int row0 = blockIdx.x * BM;

    const int ar = t >> 1;
    const int ah = t & 1;
    const int wr = t >> 4;
    const int wc = t & 15;

    float4 av0, av1, wv0, wv1;

    auto ldA = [&](int cc) {
        const float* src = (NCH == 16 && cc >= 8) ? A1 : A0;
        int kb = ((NCH == 16) ? (cc & 7) : cc) * BK;
        int r = row0 + ar;
        if (r < nrows) {
            const float* p = src + (size_t)r * DIM + kb + ah * 8;
            av0 = *(const float4*)(p);
            av1 = *(const float4*)(p + 4);
        } else {
            av0 = av1 = make_float4(0.f, 0.f, 0.f, 0.f);
        }
    };
    auto stsA = [&](int buf) {
        uint64_t* d = As + buf * AS_U64 + (ah * 8) * BM + ar;
        d[0 * BM] = dup2(av0.x); d[1 * BM] = dup2(av0.y);
        d[2 * BM] = dup2(av0.z); d[3 * BM] = dup2(av0.w);
        d[4 * BM] = dup2(av1.x); d[5 * BM] = dup2(av1.y);
        d[6 * BM] = dup2(av1.z); d[7 * BM] = dup2(av1.w);
    };
    auto ldW = [&](int cc) {
        const float* src = (NCH == 16 && cc >= 8) ? W1 : W0;
        int kb = ((NCH == 16) ? (cc & 7) : cc) * BK;
        const float* p = src + (size_t)(kb + wr) * DIM + wc * 8;
        wv0 = *(const float4*)(p);
        wv1 = *(const float4*)(p + 4);
    };
    auto stsW = [&](int buf) {
        float* d = Ws + buf * WS_F32 + wr * DIM + wc * 8;
        *(float4*)(d)     = wv0;
        *(float4*)(d + 4) = wv1;
    };

    uint64_t acc[8][4];
    #pragma unroll
    for (int i = 0; i < 8; i++)
        #pragma unroll
        for (int j = 0; j < 4; j++) acc[i][j] = 0ull;

    ldA(0); ldW(0);
    stsA(0); stsW(0);

    for (int cc = 0; cc < NCH; cc++) {
        __syncthreads();
        if (cc + 1 < NCH) { ldA(cc + 1); ldW(cc + 1); }
        const uint64_t* as = As + (cc & 1) * AS_U64 + 8 * ty;
        const float*    ws = Ws + (cc & 1) * WS_F32 + 2 * tx;
        #pragma unroll
        for (int k = 0; k < BK; k++) {
            ulonglong2 a01 = *(const ulonglong2*)(as + k * BM);
            ulonglong2 a23 = *(const ulonglong2*)(as + k * BM + 2);
            ulonglong2 a45 = *(const ulonglong2*)(as + k * BM + 4);
            ulonglong2 a67 = *(const ulonglong2*)(as + k * BM + 6);
            uint64_t w0 = *(const uint64_t*)(ws + k * DIM);
            uint64_t w1 = *(const uint64_t*)(ws + k * DIM + 32);
            uint64_t w2 = *(const uint64_t*)(ws + k * DIM + 64);
            uint64_t w3 = *(const uint64_t*)(ws + k * DIM + 96);
            ffma2(acc[0][0], a01.x, w0); ffma2(acc[0][1], a01.x, w1);
            ffma2(acc[0][2], a01.x, w2); ffma2(acc[0][3], a01.x, w3);
            ffma2(acc[1][0], a01.y, w0); ffma2(acc[1][1], a01.y, w1);
            ffma2(acc[1][2], a01.y, w2); ffma2(acc[1][3], a01.y, w3);
            ffma2(acc[2][0], a23.x, w0); ffma2(acc[2][1], a23.x, w1);
            ffma2(acc[2][2], a23.x, w2); ffma2(acc[2][3], a23.x, w3);
            ffma2(acc[3][0], a23.y, w0); ffma2(acc[3][1], a23.y, w1);
            ffma2(acc[3][2], a23.y, w2); ffma2(acc[3][3], a23.y, w3);
            ffma2(acc[4][0], a45.x, w0); ffma2(acc[4][1], a45.x, w1);
            ffma2(acc[4][2], a45.x, w2); ffma2(acc[4][3], a45.x, w3);
            ffma2(acc[5][0], a45.y, w0); ffma2(acc[5][1], a45.y, w1);
            ffma2(acc[5][2], a45.y, w2); ffma2(acc[5][3], a45.y, w3);
            ffma2(acc[6][0], a67.x, w0); ffma2(acc[6][1], a67.x, w1);
            ffma2(acc[6][2], a67.x, w2); ffma2(acc[6][3], a67.x, w3);
            ffma2(acc[7][0], a67.y, w0); ffma2(acc[7][1], a67.y, w1);
            ffma2(acc[7][2], a67.y, w2); ffma2(acc[7][3], a67.y, w3);
        }
        if (cc + 1 < NCH) { stsA((cc + 1) & 1); stsW((cc + 1) & 1); }
    }

    // ---------------- epilogue ----------------
    float2 bb[4];
    #pragma unroll
    for (int g = 0; g < 4; g++) {
        int col = 2 * tx + 32 * g;
        bb[g] = *(const float2*)(b1 + col);
        if (b2 != nullptr) {
            float2 b2v = *(const float2*)(b2 + col);
            bb[g].x += b2v.x; bb[g].y += b2v.y;
        }
    }

    #pragma unroll
    for (int i = 0; i < 8; i++) {
        int m = row0 + 8 * ty + i;
        if (m >= nrows) continue;
        #pragma unroll
        for (int g = 0; g < 4; g++) {
            int col = 2 * tx + 32 * g;
            float2 p = unpk(acc[i][g]);
            float vx = p.x + bb[g].x;
            float vy = p.y + bb[g].y;
            float2 o;
            if (EPI == 0) {
                o = make_float2(fmaxf(vx, 0.f), fmaxf(vy, 0.f));
            } else if (EPI == 1) {
                o = make_float2(vx, vy);
            } else if (EPI == 2) {
                o = make_float2(sigf(vx), sigf(vy));
                if (aux1 != nullptr) {
                    float2 xv = *(const float2*)(aux1 + (size_t)m * DIM + col);
                    o.x *= xv.x; o.y *= xv.y;
                }
            } else {  // EPI == 3: y = (1-z)*x + z*tanh(v)
                float2 zv = *(const float2*)(aux1 + (size_t)m * DIM + col);
                float2 xv = *(const float2*)(aux2 + (size_t)m * DIM + col);
                o.x = (1.f - zv.x) * xv.x + zv.x * tanhf(vx);
                o.y = (1.f - zv.y) * xv.y + zv.y * tanhf(vy);
            }
            *(float2*)(out + (size_t)m * DIM + col) = o;
        }
    }
}

// ---------------- CSR build + gather -----------------------------------------
__global__ void hist_kernel(const int* __restrict__ rows, int* __restrict__ cnt, int E) {
    int e = blockIdx.x * blockDim.x + threadIdx.x;
    if (e < E) atomicAdd(&cnt[__ldg(rows + e)], 1);
}

// single-block exclusive scan over n counters; writes offsets (in place) + head copy
__global__ void __launch_bounds__(1024)
scan_kernel(int* __restrict__ cnt, int* __restrict__ head, int n) {
    __shared__ int wsum[32];
    __shared__ int carry;
    const int tid = threadIdx.x;
    const int lane = tid & 31, w = tid >> 5;
    if (tid == 0) carry = 0;
    __syncthreads();
    for (int base = 0; base < n; base += 1024) {
        int i = base + tid;
        int v = (i < n) ? cnt[i] : 0;
        int x = v;
        #pragma unroll
        for (int d = 1; d < 32; d <<= 1) {
            int y = __shfl_up_sync(~0u, x, d);
            if (lane >= d) x += y;
        }
        if (lane == 31) wsum[w] = x;
        __syncthreads();
        if (w == 0) {
            int s = wsum[lane];
            #pragma unroll
            for (int d = 1; d < 32; d <<= 1) {
                int y = __shfl_up_sync(~0u, s, d);
                if (lane >= d) s += y;
            }
            wsum[lane] = s;
        }
        __syncthreads();
        int incl = x + (w > 0 ? wsum[w - 1] : 0) + carry;
        int excl = incl - v;
        if (i < n) { cnt[i] = excl; head[i] = excl; }
        __syncthreads();
        if (tid == 1023) carry = incl;
        __syncthreads();
    }
    if (tid == 0) cnt[n] = carry;
}

__global__ void bucket_kernel(const int* __restrict__ rows, const int* __restrict__ cols,
                              const float* __restrict__ vals, int* __restrict__ head,
                              int* __restrict__ ecol, float* __restrict__ eval, int E) {
    int e = blockIdx.x * blockDim.x + threadIdx.x;
    if (e < E) {
        int p = atomicAdd(&head[__ldg(rows + e)], 1);
        ecol[p] = __ldg(cols + e);
        eval[p] = __ldg(vals + e);
    }
}

// one warp per node: AGG[i] = sum_j eval[j] * X[ecol[j]]
__global__ void __launch_bounds__(NT)
gather_kernel(const int* __restrict__ off, const int* __restrict__ ecol,
              const float* __restrict__ eval, const float* __restrict__ X,
              float* __restrict__ AGG, int n)
{
    int node = blockIdx.x * (NT / 32) + (threadIdx.x >> 5);
    int lane = threadIdx.x & 31;
    if (node >= n) return;
    int j   = __ldg(off + node);
    int end = __ldg(off + node + 1);
    float4 acc = make_float4(0.f, 0.f, 0.f, 0.f);
    for (; j + 1 < end; j += 2) {
        int   c0 = __ldg(ecol + j),     c1 = __ldg(ecol + j + 1);
        float v0 = __ldg(eval + j),     v1 = __ldg(eval + j + 1);
        float4 x0 = reinterpret_cast<const float4*>(X + (size_t)c0 * DIM)[lane];
        float4 x1 = reinterpret_cast<const float4*>(X + (size_t)c1 * DIM)[lane];
        acc.x = fmaf(v0, x0.x, acc.x); acc.y = fmaf(v0, x0.y, acc.y);
        acc.z = fmaf(v0, x0.z, acc.z); acc.w = fmaf(v0, x0.w, acc.w);
        acc.x = fmaf(v1, x1.x, acc.x); acc.y = fmaf(v1, x1.y, acc.y);
        acc.z = fmaf(v1, x1.z, acc.z); acc.w = fmaf(v1, x1.w, acc.w);
    }
    if (j < end) {
        int   c0 = __ldg(ecol + j);
        float v0 = __ldg(eval + j);
        float4 x0 = reinterpret_cast<const float4*>(X + (size_t)c0 * DIM)[lane];
        acc.x = fmaf(v0, x0.x, acc.x); acc.y = fmaf(v0, x0.y, acc.y);
        acc.z = fmaf(v0, x0.z, acc.z); acc.w = fmaf(v0, x0.w, acc.w);
    }
    reinterpret_cast<float4*>(AGG + (size_t)node * DIM)[lane] = acc;
}

// ---------------- launch -----------------------------------------------------
extern "C" void kernel_launch(void* const* d_in, const int* in_sizes, int n_in,
                              void* d_out, int out_size)
{
    const float* x_in = (const float*)d_in[0];
    const int*   rows = (const int*)d_in[1];
    const int*   cols = (const int*)d_in[2];
    const float* vals = (const float*)d_in[3];
    const float* m1W1 = (const float*)d_in[4];
    const float* m1b1 = (const float*)d_in[5];
    const float* m1W2 = (const float*)d_in[6];
    const float* m1b2 = (const float*)d_in[7];
    const float* m2W1 = (const float*)d_in[8];
    const float* m2b1 = (const float*)d_in[9];
    const float* m2W2 = (const float*)d_in[10];
    const float* m2b2 = (const float*)d_in[11];
    const float* Wu1 = (const float*)d_in[12];
    const float* bu1 = (const float*)d_in[13];
    const float* Wu2 = (const float*)d_in[14];
    const float* bu2 = (const float*)d_in[15];
    const float* Wr1 = (const float*)d_in[16];
    const float* br1 = (const float*)d_in[17];
    const float* Wr2 = (const float*)d_in[18];
    const float* br2 = (const float*)d_in[19];
    const float* Wo1 = (const float*)d_in[20];
    const float* bo1 = (const float*)d_in[21];
    const float* Wo2 = (const float*)d_in[22];
    const float* bo2 = (const float*)d_in[23];

    int n = in_sizes[0] / DIM;
    int E = in_sizes[1];
    float* y = (float*)d_out;

    float *H, *X, *AGG, *OUT, *Z, *RX, *EVAL;
    int *OFF, *HEAD, *ECOL;
    cudaGetSymbolAddress((void**)&H, g_H);
    cudaGetSymbolAddress((void**)&X, g_X);
    cudaGetSymbolAddress((void**)&AGG, g_AGG);
    cudaGetSymbolAddress((void**)&OUT, g_OUT);
    cudaGetSymbolAddress((void**)&Z, g_Z);
    cudaGetSymbolAddress((void**)&RX, g_RX);
    cudaGetSymbolAddress((void**)&OFF, g_off);
    cudaGetSymbolAddress((void**)&HEAD, g_head);
    cudaGetSymbolAddress((void**)&ECOL, g_ecol);
    cudaGetSymbolAddress((void**)&EVAL, g_eval);

    cudaFuncSetAttribute(gemm_kernel<0, 8>,  cudaFuncAttributeMaxDynamicSharedMemorySize, SMEM_GEMM);
    cudaFuncSetAttribute(gemm_kernel<1, 8>,  cudaFuncAttributeMaxDynamicSharedMemorySize, SMEM_GEMM);
    cudaFuncSetAttribute(gemm_kernel<2, 16>, cudaFuncAttributeMaxDynamicSharedMemorySize, SMEM_GEMM);
    cudaFuncSetAttribute(gemm_kernel<3, 16>, cudaFuncAttributeMaxDynamicSharedMemorySize, SMEM_GEMM);

    int nb = (n + BM - 1) / BM;
    int eb = (E + NT - 1) / NT;

    // ---- CSR build (independent of GEMM results; runs up front) ----
    cudaMemsetAsync(OFF, 0, (size_t)(n + 1) * sizeof(int));
    hist_kernel<<<eb, NT>>>(rows, OFF, E);
    scan_kernel<<<1, 1024>>>(OFF, HEAD, n);
    bucket_kernel<<<eb, NT>>>(rows, cols, vals, HEAD, ECOL, EVAL, E);

    // H = relu(x_in @ m1W1 + b1); X = H @ m1W2 + b2
    gemm_kernel<0, 8><<<nb, NT, SMEM_GEMM>>>(x_in, nullptr, m1W1, nullptr,
                                             m1b1, nullptr, nullptr, nullptr, H, n);
    gemm_kernel<1, 8><<<nb, NT, SMEM_GEMM>>>(H, nullptr, m1W2, nullptr,
                                             m1b2, nullptr, nullptr, nullptr, X, n);
    // AGG[i] = sum_e vals[e]*X[cols[e]] over rows[e]==i  (deterministic gather)
    gather_kernel<<<(n + (NT / 32) - 1) / (NT / 32), NT>>>(OFF, ECOL, EVAL, X, AGG, n);
    // H = relu(AGG @ m2W1 + b1); OUT = H @ m2W2 + b2
    gemm_kernel<0, 8><<<nb, NT, SMEM_GEMM>>>(AGG, nullptr, m2W1, nullptr,
                                             m2b1, nullptr, nullptr, nullptr, H, n);
    gemm_kernel<1, 8><<<nb, NT, SMEM_GEMM>>>(H, nullptr, m2W2, nullptr,
                                             m2b2, nullptr, nullptr, nullptr, OUT, n);
    // Z  = sigmoid(OUT@Wu1 + X@Wu2 + bu)
    gemm_kernel<2, 16><<<nb, NT, SMEM_GEMM>>>(OUT, X, Wu1, Wu2,
                                              bu1, bu2, nullptr, nullptr, Z, n);
    // RX = sigmoid(OUT@Wr1 + X@Wr2 + br) * X
    gemm_kernel<2, 16><<<nb, NT, SMEM_GEMM>>>(OUT, X, Wr1, Wr2,
                                              br1, br2, X, nullptr, RX, n);
    // y = (1-Z)*X + Z*tanh(OUT@Wo1 + RX@Wo2 + bo)
    gemm_kernel<3, 16><<<nb, NT, SMEM_GEMM>>>(OUT, RX, Wo1, Wo2,
                                              bo1, bo2, Z, X, y, n);
}

// round 11
// speedup vs baseline: 1.5828x; 1.0200x over previous
#include <cuda_runtime.h>
#include <math.h>
#include <stdint.h>

#define DIM 128
#define MAXN 50000
#define MAXE 1600000
#define BM 64
#define BK 16
#define NT 128
#define AS_U64  (BK * BM)                 // per buffer, u64 elems (8KB)
#define WS_F32  (BK * DIM)                // per buffer, floats (8KB)
#define SMEM_GEMM (2 * AS_U64 * 8 + 2 * WS_F32 * 4)   // 32768

// scratch (device globals; allocation-free rule)
__device__ float g_H  [(size_t)MAXN * DIM];
__device__ float g_X  [(size_t)MAXN * DIM];
__device__ float g_AGG[(size_t)MAXN * DIM];
__device__ float g_OUT[(size_t)MAXN * DIM];
__device__ float g_Z  [(size_t)MAXN * DIM];
__device__ float g_RX [(size_t)MAXN * DIM];
__device__ int   g_off [MAXN + 1];
__device__ int   g_head[MAXN];
__device__ int   g_ecol[MAXE];
__device__ float g_eval[MAXE];

// ---------------- packed f32x2 helpers --------------------------------------
__device__ __forceinline__ void ffma2(uint64_t& acc, uint64_t a, uint64_t b) {
    asm("fma.rn.f32x2 %0, %1, %2, %0;" : "+l"(acc) : "l"(a), "l"(b));
}
__device__ __forceinline__ uint64_t dup2(float a) {
    uint64_t d;
    asm("mov.b64 %0, {%1, %1};" : "=l"(d) : "f"(a));
    return d;
}
__device__ __forceinline__ float2 unpk(uint64_t v) {
    float2 f;
    asm("mov.b64 {%0, %1}, %2;" : "=f"(f.x), "=f"(f.y) : "l"(v));
    return f;
}
__device__ __forceinline__ float sigf(float x) { return 1.f / (1.f + __expf(-x)); }

// ---------------- GEMM template ---------------------------------------------
// C[M x 128] = A[M x K] @ W[K x 128] + epilogue; K = NCH*16 (NCH=8 or 16).
// NT=128, BM=64: 4 blocks/SM -> 4 independent barrier domains.
// Thread (tx,ty): rows 8*ty..8*ty+7, col pairs (2*tx+32g), g=0..3.
template<int EPI, int NCH>
__global__ void __launch_bounds__(NT, 4)
gemm_kernel(const float* __restrict__ A0, const float* __restrict__ A1,
            const float* __restrict__ W0, const float* __restrict__ W1,
            const float* __restrict__ b1, const float* __restrict__ b2,
            const float* __restrict__ aux1, const float* __restrict__ aux2,
            float* __restrict__ out, int nrows)
{
    extern __shared__ char smc[];
    uint64_t* As = (uint64_t*)smc;                    // [2][BK][BM] dup'd
    float*    Ws = (float*)(smc + 2 * AS_U64 * 8);    // [2][BK][DIM] plain
    const int t  = threadIdx.x;
    const int tx = t & 15;
    const int ty = t >> 4;                            // 0..7
    const int row0 = blockIdx.x * BM;

    // loader roles
    const int ar = t >> 1;       // A row 0..63
    const int ah = t & 1;        // k half (8 floats)
    const int wr = t >> 4;       // W k-row 0..7 (handles wr and wr+8)
    const int wc = t & 15;       // col octet

    float4 av0, av1;             // A stage: 8 floats
    float4 wv[4];                // W stage: rows wr, wr+8 x 8 floats

    auto ldA = [&](int cc) {
        const float* src = (NCH == 16 && cc >= 8) ? A1 : A0;
        int kb = ((NCH == 16) ? (cc & 7) : cc) * BK;
        int r = row0 + ar;
        if (r < nrows) {
            const float* p = src + (size_t)r * DIM + kb + ah * 8;
            av0 = *(const float4*)(p);
            av1 = *(const float4*)(p + 4);
        } else {
            av0 = av1 = make_float4(0.f, 0.f, 0.f, 0.f);
        }
    };
    auto stsA = [&](int buf) {
        uint64_t* d = As + buf * AS_U64 + (ah * 8) * BM + ar;
        d[0 * BM] = dup2(av0.x); d[1 * BM] = dup2(av0.y);
        d[2 * BM] = dup2(av0.z); d[3 * BM] = dup2(av0.w);
        d[4 * BM] = dup2(av1.x); d[5 * BM] = dup2(av1.y);
        d[6 * BM] = dup2(av1.z); d[7 * BM] = dup2(av1.w);
    };
    auto ldW = [&](int cc) {
        const float* src = (NCH == 16 && cc >= 8) ? W1 : W0;
        int kb = ((NCH == 16) ? (cc & 7) : cc) * BK;
        const float* p0 = src + (size_t)(kb + wr) * DIM + wc * 8;
        const float* p1 = src + (size_t)(kb + wr + 8) * DIM + wc * 8;
        wv[0] = *(const float4*)(p0);
        wv[1] = *(const float4*)(p0 + 4);
        wv[2] = *(const float4*)(p1);
        wv[3] = *(const float4*)(p1 + 4);
    };
    auto stsW = [&](int buf) {
        float* d0 = Ws + buf * WS_F32 + wr * DIM + wc * 8;
        float* d1 = Ws + buf * WS_F32 + (wr + 8) * DIM + wc * 8;
        *(float4*)(d0)     = wv[0];
        *(float4*)(d0 + 4) = wv[1];
        *(float4*)(d1)     = wv[2];
        *(float4*)(d1 + 4) = wv[3];
    };

    uint64_t acc[8][4];
    #pragma unroll
    for (int i = 0; i < 8; i++)
        #pragma unroll
        for (int j = 0; j < 4; j++) acc[i][j] = 0ull;

    ldA(0); ldW(0);
    stsA(0); stsW(0);

    for (int cc = 0; cc < NCH; cc++) {
        __syncthreads();
        if (cc + 1 < NCH) { ldA(cc + 1); ldW(cc + 1); }
        const uint64_t* as = As + (cc & 1) * AS_U64 + 8 * ty;
        const float*    ws = Ws + (cc & 1) * WS_F32 + 2 * tx;
        #pragma unroll
        for (int k = 0; k < BK; k++) {
            ulonglong2 a01 = *(const ulonglong2*)(as + k * BM);
            ulonglong2 a23 = *(const ulonglong2*)(as + k * BM + 2);
            ulonglong2 a45 = *(const ulonglong2*)(as + k * BM + 4);
            ulonglong2 a67 = *(const ulonglong2*)(as + k * BM + 6);
            uint64_t w0 = *(const uint64_t*)(ws + k * DIM);
            uint64_t w1 = *(const uint64_t*)(ws + k * DIM + 32);
            uint64_t w2 = *(const uint64_t*)(ws + k * DIM + 64);
            uint64_t w3 = *(const uint64_t*)(ws + k * DIM + 96);
            ffma2(acc[0][0], a01.x, w0); ffma2(acc[0][1], a01.x, w1);
            ffma2(acc[0][2], a01.x, w2); ffma2(acc[0][3], a01.x, w3);
            ffma2(acc[1][0], a01.y, w0); ffma2(acc[1][1], a01.y, w1);
            ffma2(acc[1][2], a01.y, w2); ffma2(acc[1][3], a01.y, w3);
            ffma2(acc[2][0], a23.x, w0); ffma2(acc[2][1], a23.x, w1);
            ffma2(acc[2][2], a23.x, w2); ffma2(acc[2][3], a23.x, w3);
            ffma2(acc[3][0], a23.y, w0); ffma2(acc[3][1], a23.y, w1);
            ffma2(acc[3][2], a23.y, w2); ffma2(acc[3][3], a23.y, w3);
            ffma2(acc[4][0], a45.x, w0); ffma2(acc[4][1], a45.x, w1);
            ffma2(acc[4][2], a45.x, w2); ffma2(acc[4][3], a45.x, w3);
            ffma2(acc[5][0], a45.y, w0); ffma2(acc[5][1], a45.y, w1);
            ffma2(acc[5][2], a45.y, w2); ffma2(acc[5][3], a45.y, w3);
            ffma2(acc[6][0], a67.x, w0); ffma2(acc[6][1], a67.x, w1);
            ffma2(acc[6][2], a67.x, w2); ffma2(acc[6][3], a67.x, w3);
            ffma2(acc[7][0], a67.y, w0); ffma2(acc[7][1], a67.y, w1);
            ffma2(acc[7][2], a67.y, w2); ffma2(acc[7][3], a67.y, w3);
        }
        if (cc + 1 < NCH) { stsA((cc + 1) & 1); stsW((cc + 1) & 1); }
    }

    // ---------------- epilogue ----------------
    float2 bb[4];
    #pragma unroll
    for (int g = 0; g < 4; g++) {
        int col = 2 * tx + 32 * g;
        bb[g] = *(const float2*)(b1 + col);
        if (b2 != nullptr) {
            float2 b2v = *(const float2*)(b2 + col);
            bb[g].x += b2v.x; bb[g].y += b2v.y;
        }
    }

    #pragma unroll
    for (int i = 0; i < 8; i++) {
        int m = row0 + 8 * ty + i;
        if (m >= nrows) continue;
        #pragma unroll
        for (int g = 0; g < 4; g++) {
            int col = 2 * tx + 32 * g;
            float2 p = unpk(acc[i][g]);
            float vx = p.x + bb[g].x;
            float vy = p.y + bb[g].y;
            float2 o;
            if (EPI == 0) {
                o = make_float2(fmaxf(vx, 0.f), fmaxf(vy, 0.f));
            } else if (EPI == 1) {
                o = make_float2(vx, vy);
            } else if (EPI == 2) {
                o = make_float2(sigf(vx), sigf(vy));
                if (aux1 != nullptr) {
                    float2 xv = *(const float2*)(aux1 + (size_t)m * DIM + col);
                    o.x *= xv.x; o.y *= xv.y;
                }
            } else {  // EPI == 3: y = (1-z)*x + z*tanh(v)
                float2 zv = *(const float2*)(aux1 + (size_t)m * DIM + col);
                float2 xv = *(const float2*)(aux2 + (size_t)m * DIM + col);
                o.x = (1.f - zv.x) * xv.x + zv.x * tanhf(vx);
                o.y = (1.f - zv.y) * xv.y + zv.y * tanhf(vy);
            }
            *(float2*)(out + (size_t)m * DIM + col) = o;
        }
    }
}

// ---------------- CSR build + gather -----------------------------------------
__global__ void hist_kernel(const int* __restrict__ rows, int* __restrict__ cnt, int E) {
    int e = blockIdx.x * blockDim.x + threadIdx.x;
    if (e < E) atomicAdd(&cnt[__ldg(rows + e)], 1);
}

__global__ void __launch_bounds__(1024)
scan_kernel(int* __restrict__ cnt, int* __restrict__ head, int n) {
    __shared__ int wsum[32];
    __shared__ int carry;
    const int tid = threadIdx.x;
    const int lane = tid & 31, w = tid >> 5;
    if (tid == 0) carry = 0;
    __syncthreads();
    for (int base = 0; base < n; base += 1024) {
        int i = base + tid;
        int v = (i < n) ? cnt[i] : 0;
        int x = v;
        #pragma unroll
        for (int d = 1; d < 32; d <<= 1) {
            int y = __shfl_up_sync(~0u, x, d);
            if (lane >= d) x += y;
        }
        if (lane == 31) wsum[w] = x;
        __syncthreads();
        if (w == 0) {
            int s = wsum[lane];
            #pragma unroll
            for (int d = 1; d < 32; d <<= 1) {
                int y = __shfl_up_sync(~0u, s, d);
                if (lane >= d) s += y;
            }
            wsum[lane] = s;
        }
        __syncthreads();
        int incl = x + (w > 0 ? wsum[w - 1] : 0) + carry;
        int excl = incl - v;
        if (i < n) { cnt[i] = excl; head[i] = excl; }
        __syncthreads();
        if (tid == 1023) carry = incl;
        __syncthreads();
    }
    if (tid == 0) cnt[n] = carry;
}

__global__ void bucket_kernel(const int* __restrict__ rows, const int* __restrict__ cols,
                              const float* __restrict__ vals, int* __restrict__ head,
                              int* __restrict__ ecol, float* __restrict__ eval, int E) {
    int e = blockIdx.x * blockDim.x + threadIdx.x;
    if (e < E) {
        int p = atomicAdd(&head[__ldg(rows + e)], 1);
        ecol[p] = __ldg(cols + e);
        eval[p] = __ldg(vals + e);
    }
}

__global__ void __launch_bounds__(256)
gather_kernel(const int* __restrict__ off, const int* __restrict__ ecol,
              const float* __restrict__ eval, const float* __restrict__ X,
              float* __restrict__ AGG, int n)
{
    int node = blockIdx.x * 8 + (threadIdx.x >> 5);
    int lane = threadIdx.x & 31;
    if (node >= n) return;
    int j   = __ldg(off + node);
    int end = __ldg(off + node + 1);
    float4 acc = make_float4(0.f, 0.f, 0.f, 0.f);
    for (; j + 1 < end; j += 2) {
        int   c0 = __ldg(ecol + j),     c1 = __ldg(ecol + j + 1);
        float v0 = __ldg(eval + j),     v1 = __ldg(eval + j + 1);
        float4 x0 = reinterpret_cast<const float4*>(X + (size_t)c0 * DIM)[lane];
        float4 x1 = reinterpret_cast<const float4*>(X + (size_t)c1 * DIM)[lane];
        acc.x = fmaf(v0, x0.x, acc.x); acc.y = fmaf(v0, x0.y, acc.y);
        acc.z = fmaf(v0, x0.z, acc.z); acc.w = fmaf(v0, x0.w, acc.w);
        acc.x = fmaf(v1, x1.x, acc.x); acc.y = fmaf(v1, x1.y, acc.y);
        acc.z = fmaf(v1, x1.z, acc.z); acc.w = fmaf(v1, x1.w, acc.w);
    }
    if (j < end) {
        int   c0 = __ldg(ecol + j);
        float v0 = __ldg(eval + j);
        float4 x0 = reinterpret_cast<const float4*>(X + (size_t)c0 * DIM)[lane];
        acc.x = fmaf(v0, x0.x, acc.x); acc.y = fmaf(v0, x0.y, acc.y);
        acc.z = fmaf(v0, x0.z, acc.z); acc.w = fmaf(v0, x0.w, acc.w);
    }
    reinterpret_cast<float4*>(AGG + (size_t)node * DIM)[lane] = acc;
}

// ---------------- launch -----------------------------------------------------
extern "C" void kernel_launch(void* const* d_in, const int* in_sizes, int n_in,
                              void* d_out, int out_size)
{
    const float* x_in = (const float*)d_in[0];
    const int*   rows = (const int*)d_in[1];
    const int*   cols = (const int*)d_in[2];
    const float* vals = (const float*)d_in[3];
    const float* m1W1 = (const float*)d_in[4];
    const float* m1b1 = (const float*)d_in[5];
    const float* m1W2 = (const float*)d_in[6];
    const float* m1b2 = (const float*)d_in[7];
    const float* m2W1 = (const float*)d_in[8];
    const float* m2b1 = (const float*)d_in[9];
    const float* m2W2 = (const float*)d_in[10];
    const float* m2b2 = (const float*)d_in[11];
    const float* Wu1 = (const float*)d_in[12];
    const float* bu1 = (const float*)d_in[13];
    const float* Wu2 = (const float*)d_in[14];
    const float* bu2 = (const float*)d_in[15];
    const float* Wr1 = (const float*)d_in[16];
    const float* br1 = (const float*)d_in[17];
    const float* Wr2 = (const float*)d_in[18];
    const float* br2 = (const float*)d_in[19];
    const float* Wo1 = (const float*)d_in[20];
    const float* bo1 = (const float*)d_in[21];
    const float* Wo2 = (const float*)d_in[22];
    const float* bo2 = (const float*)d_in[23];

    int n = in_sizes[0] / DIM;
    int E = in_sizes[1];
    float* y = (float*)d_out;

    float *H, *X, *AGG, *OUT, *Z, *RX, *EVAL;
    int *OFF, *HEAD, *ECOL;
    cudaGetSymbolAddress((void**)&H, g_H);
    cudaGetSymbolAddress((void**)&X, g_X);
    cudaGetSymbolAddress((void**)&AGG, g_AGG);
    cudaGetSymbolAddress((void**)&OUT, g_OUT);
    cudaGetSymbolAddress((void**)&Z, g_Z);
    cudaGetSymbolAddress((void**)&RX, g_RX);
    cudaGetSymbolAddress((void**)&OFF, g_off);
    cudaGetSymbolAddress((void**)&HEAD, g_head);
    cudaGetSymbolAddress((void**)&ECOL, g_ecol);
    cudaGetSymbolAddress((void**)&EVAL, g_eval);

    cudaFuncSetAttribute(gemm_kernel<0, 8>,  cudaFuncAttributeMaxDynamicSharedMemorySize, SMEM_GEMM);
    cudaFuncSetAttribute(gemm_kernel<1, 8>,  cudaFuncAttributeMaxDynamicSharedMemorySize, SMEM_GEMM);
    cudaFuncSetAttribute(gemm_kernel<2, 16>, cudaFuncAttributeMaxDynamicSharedMemorySize, SMEM_GEMM);
    cudaFuncSetAttribute(gemm_kernel<3, 16>, cudaFuncAttributeMaxDynamicSharedMemorySize, SMEM_GEMM);

    int nb = (n + BM - 1) / BM;
    int eb = (E + 255) / 256;

    // ---- CSR build ----
    cudaMemsetAsync(OFF, 0, (size_t)(n + 1) * sizeof(int));
    hist_kernel<<<eb, 256>>>(rows, OFF, E);
    scan_kernel<<<1, 1024>>>(OFF, HEAD, n);
    bucket_kernel<<<eb, 256>>>(rows, cols, vals, HEAD, ECOL, EVAL, E);

    // H = relu(x_in @ m1W1 + b1); X = H @ m1W2 + b2
    gemm_kernel<0, 8><<<nb, NT, SMEM_GEMM>>>(x_in, nullptr, m1W1, nullptr,
                                             m1b1, nullptr, nullptr, nullptr, H, n);
    gemm_kernel<1, 8><<<nb, NT, SMEM_GEMM>>>(H, nullptr, m1W2, nullptr,
                                             m1b2, nullptr, nullptr, nullptr, X, n);
    // AGG[i] = sum_e vals[e]*X[cols[e]] over rows[e]==i  (deterministic gather)
    gather_kernel<<<(n + 7) / 8, 256>>>(OFF, ECOL, EVAL, X, AGG, n);
    // H = relu(AGG @ m2W1 + b1); OUT = H @ m2W2 + b2
    gemm_kernel<0, 8><<<nb, NT, SMEM_GEMM>>>(AGG, nullptr, m2W1, nullptr,
                                             m2b1, nullptr, nullptr, nullptr, H, n);
    gemm_kernel<1, 8><<<nb, NT, SMEM_GEMM>>>(H, nullptr, m2W2, nullptr,
                                             m2b2, nullptr, nullptr, nullptr, OUT, n);
    // Z  = sigmoid(OUT@Wu1 + X@Wu2 + bu)
    gemm_kernel<2, 16><<<nb, NT, SMEM_GEMM>>>(OUT, X, Wu1, Wu2,
                                              bu1, bu2, nullptr, nullptr, Z, n);
    // RX = sigmoid(OUT@Wr1 + X@Wr2 + br) * X
    gemm_kernel<2, 16><<<nb, NT, SMEM_GEMM>>>(OUT, X, Wr1, Wr2,
                                              br1, br2, X, nullptr, RX, n);
    // y = (1-Z)*X + Z*tanh(OUT@Wo1 + RX@Wo2 + bo)
    gemm_kernel<3, 16><<<nb, NT, SMEM_GEMM>>>(OUT, RX, Wo1, Wo2,
                                              bo1, bo2, Z, X, y, n);
}